// round 14
// baseline (speedup 1.0000x reference)
#include <cuda_runtime.h>
#include <cuda_fp16.h>
#include <math.h>
#include <stdint.h>

#define BATCH 2
#define SEQ   2048
#define DM    1024
#define NH    16
#define HD    64
#define HALF  256

// ---------------- scratch ----------------
__device__ __half g_qkvh[BATCH * SEQ * 3 * DM];  // [B,N,3,H,Dh] fp16
__device__ __half g_attnh[BATCH * SEQ * DM];     // attention out, fp16
__device__ __half g_xh[BATCH * SEQ * DM];        // x in fp16
__device__ __half g_wqkvh[DM * 3 * DM];          // [C,3C] natural fp16
__device__ __half g_wprojh[DM * DM];             // [C,C]  natural fp16
__device__ int    g_ctr[2];                      // persistent tile queues

// ---------------- helpers ----------------
__device__ __forceinline__ uint32_t smem_u32(const void* p) {
    uint32_t a;
    asm("{ .reg .u64 t; cvta.to.shared.u64 t, %1; cvt.u32.u64 %0, t; }"
        : "=r"(a) : "l"(p));
    return a;
}
__device__ __forceinline__ void cpa16(uint32_t dst, const void* src) {
    asm volatile("cp.async.cg.shared.global [%0], [%1], 16;"
                 :: "r"(dst), "l"(src));
}
#define CP_COMMIT() asm volatile("cp.async.commit_group;" ::: "memory")
#define CP_WAIT(n)  asm volatile("cp.async.wait_group %0;" :: "n"(n) : "memory")

__device__ __forceinline__ void ldsm4(uint32_t& r0, uint32_t& r1,
                                      uint32_t& r2, uint32_t& r3,
                                      uint32_t addr) {
    asm volatile("ldmatrix.sync.aligned.m8n8.x4.shared.b16 {%0,%1,%2,%3}, [%4];"
                 : "=r"(r0), "=r"(r1), "=r"(r2), "=r"(r3) : "r"(addr));
}
__device__ __forceinline__ void ldsm4t(uint32_t& r0, uint32_t& r1,
                                       uint32_t& r2, uint32_t& r3,
                                       uint32_t addr) {
    asm volatile("ldmatrix.sync.aligned.m8n8.x4.trans.shared.b16 {%0,%1,%2,%3}, [%4];"
                 : "=r"(r0), "=r"(r1), "=r"(r2), "=r"(r3) : "r"(addr));
}
__device__ __forceinline__ void mma_f16(float* c, const uint32_t* a,
                                        const uint32_t* b) {
    asm volatile(
        "mma.sync.aligned.m16n8k16.row.col.f32.f16.f16.f32 "
        "{%0,%1,%2,%3}, {%4,%5,%6,%7}, {%8,%9}, {%0,%1,%2,%3};"
        : "+f"(c[0]), "+f"(c[1]), "+f"(c[2]), "+f"(c[3])
        : "r"(a[0]), "r"(a[1]), "r"(a[2]), "r"(a[3]), "r"(b[0]), "r"(b[1]));
}

// ---------------- prep: fused f32->f16 convert + counter reset ----------
__device__ __forceinline__ uint4 cvt8(const float4* p) {
    float4 a = p[0], b = p[1];
    __half2 h0 = __floats2half2_rn(a.x, a.y);
    __half2 h1 = __floats2half2_rn(a.z, a.w);
    __half2 h2 = __floats2half2_rn(b.x, b.y);
    __half2 h3 = __floats2half2_rn(b.z, b.w);
    uint4 o;
    o.x = *(uint32_t*)&h0; o.y = *(uint32_t*)&h1;
    o.z = *(uint32_t*)&h2; o.w = *(uint32_t*)&h3;
    return o;
}
__global__ void convert3_kernel(const float4* __restrict__ a, uint4* oa, int na,
                                const float4* __restrict__ b, uint4* ob, int nb,
                                const float4* __restrict__ c, uint4* oc, int nc)
{
    if (blockIdx.x == 0 && threadIdx.x == 0) { g_ctr[0] = 0; g_ctr[1] = 0; }
    int i = blockIdx.x * blockDim.x + threadIdx.x;
    if (i < na)                { oa[i] = cvt8(a + 2 * i); return; }
    i -= na;
    if (i < nb)                { ob[i] = cvt8(b + 2 * i); return; }
    i -= nb;
    if (i < nc)                { oc[i] = cvt8(c + 2 * i); }
}

// ---------------- fp16 mma.sync GEMM, persistent tile queue -------------
// CTA 128x128 tile, BK=64, 3 stages, 8 warps (4m x 2n), warp tile 32x64.
#define ATILE_B (128 * 144)                 // 18432
#define BTILE_B (64 * 272)                  // 17408
#define STAGE_B (ATILE_B + BTILE_B)         // 35840
#define GSTAGES 3
#define GEMM_SMEM (GSTAGES * STAGE_B)       // 107520

__global__ void __launch_bounds__(256, 2)
gemm_f16_kernel(const __half* __restrict__ A, const __half* __restrict__ W,
                void* __restrict__ Cv, const float* __restrict__ bias,
                int M, int N, int K, int out_half,
                int nx, int ntiles, int cidx)
{
    extern __shared__ __half hsm[];
    __shared__ int s_tile;
    const uint32_t sbase = smem_u32(hsm);

    const int tid = threadIdx.x;
    const int wid = tid >> 5, lane = tid & 31;
    const int wm = wid >> 1;
    const int wn = wid & 1;
    const int g = lane >> 2, t = lane & 3;
    const int q = lane >> 3, rl = lane & 7;
    const int NC = K / 64;

    // ldmatrix lane offsets (tile-independent)
    uint32_t aoff[2], boff[4];
    #pragma unroll
    for (int mt = 0; mt < 2; mt++)
        aoff[mt] = (uint32_t)((wm * 32 + mt * 16 + (q & 1) * 8 + rl) * 144 +
                              (q >> 1) * 16);
    #pragma unroll
    for (int j = 0; j < 4; j++)
        boff[j] = (uint32_t)(((q & 1) * 8 + rl) * 272 +
                             (wn * 64 + j * 16) * 2 + (q >> 1) * 16) + ATILE_B;

    for (;;) {
        if (tid == 0) s_tile = atomicAdd(&g_ctr[cidx], 1);
        __syncthreads();           // broadcast + end-of-previous-tile guard
        const int tile = s_tile;
        if (tile >= ntiles) break;
        const int m0 = (tile / nx) * 128;
        const int n0 = (tile % nx) * 128;

        const __half* Ab = A + (size_t)m0 * K;
        const __half* Wn = W + n0;

        auto load_chunk = [&](int k0, int slot) {
            const uint32_t st = sbase + (uint32_t)(slot * STAGE_B);
            const uint32_t bb = st + ATILE_B;
            #pragma unroll
            for (int i = 0; i < 4; i++) {
                int idx = tid + i * 256;
                int r = idx >> 3, c16 = idx & 7;
                cpa16(st + (uint32_t)(r * 144 + c16 * 16),
                      Ab + (size_t)r * K + k0 + c16 * 8);
            }
            #pragma unroll
            for (int i = 0; i < 4; i++) {
                int idx = tid + i * 256;
                int r = idx >> 4, c16 = idx & 15;
                cpa16(bb + (uint32_t)(r * 272 + c16 * 16),
                      Wn + (size_t)(k0 + r) * N + c16 * 8);
            }
        };

        float acc[2][8][4];
        #pragma unroll
        for (int i = 0; i < 2; i++)
            #pragma unroll
            for (int j = 0; j < 8; j++)
                #pragma unroll
                for (int r = 0; r < 4; r++) acc[i][j][r] = 0.f;

        load_chunk(0, 0); CP_COMMIT();
        load_chunk(64, 1); CP_COMMIT();

        int slot_use = 0, slot_load = 2;
        for (int c = 0; c < NC; c++) {
            CP_WAIT(1);
            __syncthreads();
            if (c + 2 < NC) {
                load_chunk((c + 2) * 64, slot_load);
                slot_load = (slot_load + 1 == GSTAGES) ? 0 : slot_load + 1;
            }
            CP_COMMIT();

            const uint32_t st = sbase + (uint32_t)(slot_use * STAGE_B);
            slot_use = (slot_use + 1 == GSTAGES) ? 0 : slot_use + 1;

            #pragma unroll
            for (int ks = 0; ks < 4; ks++) {
                uint32_t a[2][4];
                ldsm4(a[0][0], a[0][1], a[0][2], a[0][3],
                      st + ks * 32 + aoff[0]);
                ldsm4(a[1][0], a[1][1], a[1][2], a[1][3],
                      st + ks * 32 + aoff[1]);
                const uint32_t badd = st + (uint32_t)(ks * 16 * 272);
                #pragma unroll
                for (int j = 0; j < 4; j++) {
                    uint32_t b0, b1, b2, b3;
                    ldsm4t(b0, b1, b2, b3, badd + boff[j]);
                    uint32_t be[2] = { b0, b1 }, bo[2] = { b2, b3 };
                    mma_f16(acc[0][2 * j],     a[0], be);
                    mma_f16(acc[1][2 * j],     a[1], be);
                    mma_f16(acc[0][2 * j + 1], a[0], bo);
                    mma_f16(acc[1][2 * j + 1], a[1], bo);
                }
            }
        }

        if (out_half) {
            __half* Cb = (__half*)Cv + (size_t)m0 * N + n0;
            #pragma unroll
            for (int mt = 0; mt < 2; mt++) {
                const int r0 = wm * 32 + mt * 16 + g;
                #pragma unroll
                for (int nt = 0; nt < 8; nt++) {
                    const int col = wn * 64 + nt * 8 + t * 2;
                    *(__half2*)(Cb + (size_t)r0 * N + col) =
                        __floats2half2_rn(acc[mt][nt][0], acc[mt][nt][1]);
                    *(__half2*)(Cb + (size_t)(r0 + 8) * N + col) =
                        __floats2half2_rn(acc[mt][nt][2], acc[mt][nt][3]);
                }
            }
        } else {
            float* Cb = (float*)Cv + (size_t)m0 * N + n0;
            #pragma unroll
            for (int mt = 0; mt < 2; mt++) {
                const int r0 = wm * 32 + mt * 16 + g;
                #pragma unroll
                for (int nt = 0; nt < 8; nt++) {
                    const int col = wn * 64 + nt * 8 + t * 2;
                    float b0 = 0.f, b1 = 0.f;
                    if (bias) { b0 = bias[n0 + col]; b1 = bias[n0 + col + 1]; }
                    *(float2*)(Cb + (size_t)r0 * N + col) =
                        make_float2(acc[mt][nt][0] + b0, acc[mt][nt][1] + b1);
                    *(float2*)(Cb + (size_t)(r0 + 8) * N + col) =
                        make_float2(acc[mt][nt][2] + b0, acc[mt][nt][3] + b1);
                }
            }
        }
    }
}

// ---------------------------------------------------------------------------
// Banded flash attention, fp16 MMA (R11 64-query version — best known).
// ---------------------------------------------------------------------------
#define AHL 72
#define ABUF (64 * AHL * 2)
#define ATT_SMEM (8 * ABUF)              // 73728

__global__ void __launch_bounds__(128) attn_f16_kernel(
    const __half* __restrict__ qkvh, __half* __restrict__ out)
{
    extern __shared__ __half hs[];
    const uint32_t sb = smem_u32(hs);
    const uint32_t sQ = sb;
    const uint32_t sK = sb + ABUF;
    const uint32_t sV = sb + 4 * ABUF;
    const uint32_t sP = sb + 7 * ABUF;

    const int tid = threadIdx.x;
    const int w = tid >> 5, lane = tid & 31;
    const int g = lane >> 2, t = lane & 3;
    const int q = lane >> 3, rl = lane & 7;
    const int n0 = blockIdx.x * 64;
    const int h  = blockIdx.y;
    const int b  = blockIdx.z;
    const float scale = 0.125f;

    const __half* base = qkvh + (size_t)b * SEQ * 3 * DM + h * HD;

    const int jlo = max(0, n0 - HALF);
    const int jhi = min(SEQ, n0 + 64 + HALF);
    const int NT = (jhi - jlo) >> 6;

    auto load_rows = [&](uint32_t dst, int j0, int sel) {
        #pragma unroll
        for (int i = 0; i < 4; i++) {
            int idx = tid + i * 128;
            int r = idx >> 3, c16 = idx & 7;
            cpa16(dst + (uint32_t)(r * 144 + c16 * 16),
                  base + (size_t)(j0 + r) * 3 * DM + sel * DM + c16 * 8);
        }
    };

    load_rows(sQ, n0, 0);
    load_rows(sK, jlo, 1);
    load_rows(sV, jlo, 2);
    CP_COMMIT();
    if (1 < NT) {
        load_rows(sK + ABUF, jlo + 64, 1);
        load_rows(sV + ABUF, jlo + 64, 2);
    }
    CP_COMMIT();

    const uint32_t aoff = (uint32_t)((16 * w + (q & 1) * 8 + rl) * 144 +
                                     (q >> 1) * 16);
    uint32_t boffK[4], vboff[4];
    #pragma unroll
    for (int jt = 0; jt < 4; jt++)
        boffK[jt] = (uint32_t)(((2 * jt + (q >> 1)) * 8 + rl) * 144 +
                               (q & 1) * 16);
    #pragma unroll
    for (int dt = 0; dt < 4; dt++)
        vboff[dt] = (uint32_t)(((q & 1) * 8 + rl) * 144 + dt * 32 +
                               (q >> 1) * 16);

    float o[8][4];
    #pragma unroll
    for (int dt = 0; dt < 8; dt++)
        #pragma unroll
        for (int r = 0; r < 4; r++) o[dt][r] = 0.f;
    float m0 = -INFINITY, m1 = -INFINITY, l0 = 0.f, l1 = 0.f;

    const int i0 = n0 + w * 16 + g;
    const int i1 = i0 + 8;
    const int rowP0 = (16 * w + g) * AHL;

    int slot = 0, slot_load = 2;
    for (int c = 0; c < NT; c++) {
        const int j0 = jlo + c * 64;
        CP_WAIT(1);
        __syncthreads();
        if (c + 2 < NT) {
            load_rows(sK + slot_load * ABUF, j0 + 128, 1);
            load_rows(sV + slot_load * ABUF, j0 + 128, 2);
            slot_load = (slot_load + 1 == 3) ? 0 : slot_load + 1;
        }
        CP_COMMIT();

        const uint32_t kslot = sK + slot * ABUF;
        const uint32_t vslot = sV + slot * ABUF;
        slot = (slot + 1 == 3) ? 0 : slot + 1;

        float s[8][4];
        #pragma unroll
        for (int nt = 0; nt < 8; nt++)
            #pragma unroll
            for (int r = 0; r < 4; r++) s[nt][r] = 0.f;

        #pragma unroll
        for (int ks = 0; ks < 4; ks++) {
            uint32_t a[4];
            ldsm4(a[0], a[1], a[2], a[3], sQ + aoff + ks * 32);
            #pragma unroll
            for (int jt = 0; jt < 4; jt++) {
                uint32_t b0, b1, b2, b3;
                ldsm4(b0, b1, b2, b3, kslot + boffK[jt] + ks * 32);
                uint32_t be[2] = { b0, b1 }, bo[2] = { b2, b3 };
                mma_f16(s[2 * jt], a, be);
                mma_f16(s[2 * jt + 1], a, bo);
            }
        }

        const bool masked = (j0 - n0 == HALF) || (n0 - j0 == HALF);
        #pragma unroll
        for (int nt = 0; nt < 8; nt++) {
            #pragma unroll
            for (int r = 0; r < 4; r++) s[nt][r] *= scale;
            if (masked) {
                const int jc = j0 + 8 * nt + 2 * t;
                if (abs(i0 - jc) > HALF)       s[nt][0] = -INFINITY;
                if (abs(i0 - (jc + 1)) > HALF) s[nt][1] = -INFINITY;
                if (abs(i1 - jc) > HALF)       s[nt][2] = -INFINITY;
                if (abs(i1 - (jc + 1)) > HALF) s[nt][3] = -INFINITY;
            }
        }
        float mx0 = -INFINITY, mx1 = -INFINITY;
        #pragma unroll
        for (int nt = 0; nt < 8; nt++) {
            mx0 = fmaxf(mx0, fmaxf(s[nt][0], s[nt][1]));
            mx1 = fmaxf(mx1, fmaxf(s[nt][2], s[nt][3]));
        }
        mx0 = fmaxf(mx0, __shfl_xor_sync(0xffffffffu, mx0, 1));
        mx0 = fmaxf(mx0, __shfl_xor_sync(0xffffffffu, mx0, 2));
        mx1 = fmaxf(mx1, __shfl_xor_sync(0xffffffffu, mx1, 1));
        mx1 = fmaxf(mx1, __shfl_xor_sync(0xffffffffu, mx1, 2));
        const float nm0 = fmaxf(m0, mx0), nm1 = fmaxf(m1, mx1);
        const float corr0 = __expf(m0 - nm0), corr1 = __expf(m1 - nm1);
        m0 = nm0; m1 = nm1;

        float sum0 = 0.f, sum1 = 0.f;
        __half* Ph = hs + (sP - sb) / 2;
        #pragma unroll
        for (int nt = 0; nt < 8; nt++) {
            s[nt][0] = __expf(s[nt][0] - nm0);
            s[nt][1] = __expf(s[nt][1] - nm0);
            s[nt][2] = __expf(s[nt][2] - nm1);
            s[nt][3] = __expf(s[nt][3] - nm1);
            sum0 += s[nt][0] + s[nt][1];
            sum1 += s[nt][2] + s[nt][3];
            const int pc = rowP0 + 8 * nt + 2 * t;
            *(__half2*)(Ph + pc) = __floats2half2_rn(s[nt][0], s[nt][1]);
            *(__half2*)(Ph + pc + 8 * AHL) = __floats2half2_rn(s[nt][2], s[nt][3]);
        }
        sum0 += __shfl_xor_sync(0xffffffffu, sum0, 1);
        sum0 += __shfl_xor_sync(0xffffffffu, sum0, 2);
        sum1 += __shfl_xor_sync(0xffffffffu, sum1, 1);
        sum1 += __shfl_xor_sync(0xffffffffu, sum1, 2);
        l0 = l0 * corr0 + sum0;
        l1 = l1 * corr1 + sum1;
        #pragma unroll
        for (int dt = 0; dt < 8; dt++) {
            o[dt][0] *= corr0; o[dt][1] *= corr0;
            o[dt][2] *= corr1; o[dt][3] *= corr1;
        }
        __syncwarp();

        #pragma unroll
        for (int ks = 0; ks < 4; ks++) {
            uint32_t a[4];
            ldsm4(a[0], a[1], a[2], a[3], sP + aoff + ks * 32);
            #pragma unroll
            for (int dt = 0; dt < 4; dt++) {
                uint32_t r0, r1, r2, r3;
                ldsm4t(r0, r1, r2, r3, vslot + vboff[dt] + ks * 16 * 144);
                uint32_t be[2] = { r0, r1 }, bo[2] = { r2, r3 };
                mma_f16(o[2 * dt], a, be);
                mma_f16(o[2 * dt + 1], a, bo);
            }
        }
    }

    const float inv0 = 1.f / l0, inv1 = 1.f / l1;
    __half* o0 = out + ((size_t)(b * SEQ + i0)) * DM + h * HD;
    __half* o1 = o0 + (size_t)8 * DM;
    #pragma unroll
    for (int dt = 0; dt < 8; dt++) {
        const int col = 8 * dt + 2 * t;
        *(__half2*)(o0 + col) = __floats2half2_rn(o[dt][0] * inv0,
                                                  o[dt][1] * inv0);
        *(__half2*)(o1 + col) = __floats2half2_rn(o[dt][2] * inv1,
                                                  o[dt][3] * inv1);
    }
}

// ---------------------------------------------------------------------------
extern "C" void kernel_launch(void* const* d_in, const int* in_sizes, int n_in,
                              void* d_out, int out_size)
{
    const float* x     = (const float*)d_in[0];
    const float* Wqkv  = (const float*)d_in[1];
    const float* Wproj = (const float*)d_in[2];
    const float* bproj = (const float*)d_in[3];
    float* out = (float*)d_out;

    __half *qkvh, *attnh, *xh, *wqkvh, *wprojh;
    cudaGetSymbolAddress((void**)&qkvh, g_qkvh);
    cudaGetSymbolAddress((void**)&attnh, g_attnh);
    cudaGetSymbolAddress((void**)&xh, g_xh);
    cudaGetSymbolAddress((void**)&wqkvh, g_wqkvh);
    cudaGetSymbolAddress((void**)&wprojh, g_wprojh);

    const int M = BATCH * SEQ;
    cudaFuncSetAttribute(attn_f16_kernel,
                         cudaFuncAttributeMaxDynamicSharedMemorySize,
                         ATT_SMEM);
    cudaFuncSetAttribute(gemm_f16_kernel,
                         cudaFuncAttributeMaxDynamicSharedMemorySize,
                         GEMM_SMEM);

    // 0) prep: fused f32->f16 convert + tile-queue reset
    {
        const int na = M * DM / 8;
        const int nb = DM * 3 * DM / 8;
        const int nc = DM * DM / 8;
        const int total = na + nb + nc;
        convert3_kernel<<<(total + 255) / 256, 256>>>(
            (const float4*)x,     (uint4*)xh,     na,
            (const float4*)Wqkv,  (uint4*)wqkvh,  nb,
            (const float4*)Wproj, (uint4*)wprojh, nc);
    }
    // 1) QKV projection -> fp16 (persistent: 296 CTAs over 768 tiles)
    {
        const int ntiles = (3 * DM / 128) * (M / 128);   // 24*32 = 768
        gemm_f16_kernel<<<296, 256, GEMM_SMEM>>>(xh, wqkvh, qkvh, nullptr,
                                                 M, 3 * DM, DM, 1,
                                                 3 * DM / 128, ntiles, 0);
    }
    // 2) banded attention (64-query CTAs) -> fp16
    {
        dim3 grid(SEQ / 64, NH, BATCH);
        attn_f16_kernel<<<grid, 128, ATT_SMEM>>>(qkvh, attnh);
    }
    // 3) output projection + bias -> fp32 (256 tiles, single wave)
    {
        const int ntiles = (DM / 128) * (M / 128);       // 8*32 = 256
        gemm_f16_kernel<<<256, 256, GEMM_SMEM>>>(attnh, wprojh, out, bproj,
                                                 M, DM, DM, 0,
                                                 DM / 128, ntiles, 1);
    }
}

// round 15
// speedup vs baseline: 1.0451x; 1.0451x over previous
#include <cuda_runtime.h>
#include <cuda_fp16.h>
#include <math.h>
#include <stdint.h>

#define BATCH 2
#define SEQ   2048
#define DM    1024
#define NH    16
#define HD    64
#define HALF  256

// ---------------- scratch ----------------
__device__ __half g_qkvh[BATCH * SEQ * 3 * DM];  // [B,N,3,H,Dh] fp16
__device__ __half g_attnh[BATCH * SEQ * DM];     // attention out, fp16
__device__ __half g_xh[BATCH * SEQ * DM];        // x in fp16
__device__ __half g_wqkvh[DM * 3 * DM];          // [C,3C] natural fp16
__device__ __half g_wprojh[DM * DM];             // [C,C]  natural fp16

// ---------------- helpers ----------------
__device__ __forceinline__ uint32_t smem_u32(const void* p) {
    uint32_t a;
    asm("{ .reg .u64 t; cvta.to.shared.u64 t, %1; cvt.u32.u64 %0, t; }"
        : "=r"(a) : "l"(p));
    return a;
}
__device__ __forceinline__ void cpa16(uint32_t dst, const void* src) {
    asm volatile("cp.async.cg.shared.global [%0], [%1], 16;"
                 :: "r"(dst), "l"(src));
}
#define CP_COMMIT() asm volatile("cp.async.commit_group;" ::: "memory")
#define CP_WAIT(n)  asm volatile("cp.async.wait_group %0;" :: "n"(n) : "memory")

__device__ __forceinline__ void ldsm4(uint32_t& r0, uint32_t& r1,
                                      uint32_t& r2, uint32_t& r3,
                                      uint32_t addr) {
    asm volatile("ldmatrix.sync.aligned.m8n8.x4.shared.b16 {%0,%1,%2,%3}, [%4];"
                 : "=r"(r0), "=r"(r1), "=r"(r2), "=r"(r3) : "r"(addr));
}
__device__ __forceinline__ void ldsm4t(uint32_t& r0, uint32_t& r1,
                                       uint32_t& r2, uint32_t& r3,
                                       uint32_t addr) {
    asm volatile("ldmatrix.sync.aligned.m8n8.x4.trans.shared.b16 {%0,%1,%2,%3}, [%4];"
                 : "=r"(r0), "=r"(r1), "=r"(r2), "=r"(r3) : "r"(addr));
}
__device__ __forceinline__ void mma_f16(float* c, const uint32_t* a,
                                        const uint32_t* b) {
    asm volatile(
        "mma.sync.aligned.m16n8k16.row.col.f32.f16.f16.f32 "
        "{%0,%1,%2,%3}, {%4,%5,%6,%7}, {%8,%9}, {%0,%1,%2,%3};"
        : "+f"(c[0]), "+f"(c[1]), "+f"(c[2]), "+f"(c[3])
        : "r"(a[0]), "r"(a[1]), "r"(a[2]), "r"(a[3]), "r"(b[0]), "r"(b[1]));
}
__device__ __forceinline__ uint32_t packh2(float a, float b) {
    __half2 h = __floats2half2_rn(a, b);
    return *(uint32_t*)&h;
}

// ---------------- prep: one fused f32->f16 convert over 3 arrays ---------
__device__ __forceinline__ uint4 cvt8(const float4* p) {
    float4 a = p[0], b = p[1];
    __half2 h0 = __floats2half2_rn(a.x, a.y);
    __half2 h1 = __floats2half2_rn(a.z, a.w);
    __half2 h2 = __floats2half2_rn(b.x, b.y);
    __half2 h3 = __floats2half2_rn(b.z, b.w);
    uint4 o;
    o.x = *(uint32_t*)&h0; o.y = *(uint32_t*)&h1;
    o.z = *(uint32_t*)&h2; o.w = *(uint32_t*)&h3;
    return o;
}
__global__ void convert3_kernel(const float4* __restrict__ a, uint4* oa, int na,
                                const float4* __restrict__ b, uint4* ob, int nb,
                                const float4* __restrict__ c, uint4* oc, int nc)
{
    int i = blockIdx.x * blockDim.x + threadIdx.x;
    if (i < na)                { oa[i] = cvt8(a + 2 * i); return; }
    i -= na;
    if (i < nb)                { ob[i] = cvt8(b + 2 * i); return; }
    i -= nb;
    if (i < nc)                { oc[i] = cvt8(c + 2 * i); }
}

// ---------------- fp16 mma.sync GEMM (R11 config — best known) -----------
#define ATILE_B (128 * 144)                 // 18432
#define BTILE_B (64 * 272)                  // 17408
#define STAGE_B (ATILE_B + BTILE_B)         // 35840
#define GSTAGES 3
#define GEMM_SMEM (GSTAGES * STAGE_B)       // 107520

__global__ void __launch_bounds__(256, 2)
gemm_f16_kernel(const __half* __restrict__ A, const __half* __restrict__ W,
                void* __restrict__ Cv, const float* __restrict__ bias,
                int M, int N, int K, int out_half)
{
    extern __shared__ __half hsm[];
    const uint32_t sbase = smem_u32(hsm);

    const int tid = threadIdx.x;
    const int wid = tid >> 5, lane = tid & 31;
    const int wm = wid >> 1;
    const int wn = wid & 1;
    const int g = lane >> 2, t = lane & 3;
    const int q = lane >> 3, rl = lane & 7;
    const int m0 = blockIdx.y * 128, n0 = blockIdx.x * 128;

    const __half* Ab = A + (size_t)m0 * K;
    const __half* Wn = W + n0;
    const int NC = K / 64;

    auto load_chunk = [&](int k0, int slot) {
        const uint32_t st = sbase + (uint32_t)(slot * STAGE_B);
        const uint32_t bb = st + ATILE_B;
        #pragma unroll
        for (int i = 0; i < 4; i++) {
            int idx = tid + i * 256;
            int r = idx >> 3, c16 = idx & 7;
            cpa16(st + (uint32_t)(r * 144 + c16 * 16),
                  Ab + (size_t)r * K + k0 + c16 * 8);
        }
        #pragma unroll
        for (int i = 0; i < 4; i++) {
            int idx = tid + i * 256;
            int r = idx >> 4, c16 = idx & 15;
            cpa16(bb + (uint32_t)(r * 272 + c16 * 16),
                  Wn + (size_t)(k0 + r) * N + c16 * 8);
        }
    };

    uint32_t aoff[2], boff[4];
    #pragma unroll
    for (int mt = 0; mt < 2; mt++)
        aoff[mt] = (uint32_t)((wm * 32 + mt * 16 + (q & 1) * 8 + rl) * 144 +
                              (q >> 1) * 16);
    #pragma unroll
    for (int j = 0; j < 4; j++)
        boff[j] = (uint32_t)(((q & 1) * 8 + rl) * 272 +
                             (wn * 64 + j * 16) * 2 + (q >> 1) * 16) + ATILE_B;

    float acc[2][8][4];
    #pragma unroll
    for (int i = 0; i < 2; i++)
        #pragma unroll
        for (int j = 0; j < 8; j++)
            #pragma unroll
            for (int r = 0; r < 4; r++) acc[i][j][r] = 0.f;

    load_chunk(0, 0); CP_COMMIT();
    load_chunk(64, 1); CP_COMMIT();

    int slot_use = 0, slot_load = 2;
    for (int c = 0; c < NC; c++) {
        CP_WAIT(1);
        __syncthreads();
        if (c + 2 < NC) {
            load_chunk((c + 2) * 64, slot_load);
            slot_load = (slot_load + 1 == GSTAGES) ? 0 : slot_load + 1;
        }
        CP_COMMIT();

        const uint32_t st = sbase + (uint32_t)(slot_use * STAGE_B);
        slot_use = (slot_use + 1 == GSTAGES) ? 0 : slot_use + 1;

        #pragma unroll
        for (int ks = 0; ks < 4; ks++) {
            uint32_t a[2][4];
            ldsm4(a[0][0], a[0][1], a[0][2], a[0][3],
                  st + ks * 32 + aoff[0]);
            ldsm4(a[1][0], a[1][1], a[1][2], a[1][3],
                  st + ks * 32 + aoff[1]);
            const uint32_t badd = st + (uint32_t)(ks * 16 * 272);
            #pragma unroll
            for (int j = 0; j < 4; j++) {
                uint32_t b0, b1, b2, b3;
                ldsm4t(b0, b1, b2, b3, badd + boff[j]);
                uint32_t be[2] = { b0, b1 }, bo[2] = { b2, b3 };
                mma_f16(acc[0][2 * j],     a[0], be);
                mma_f16(acc[1][2 * j],     a[1], be);
                mma_f16(acc[0][2 * j + 1], a[0], bo);
                mma_f16(acc[1][2 * j + 1], a[1], bo);
            }
        }
    }

    if (out_half) {
        __half* Cb = (__half*)Cv + (size_t)m0 * N + n0;
        #pragma unroll
        for (int mt = 0; mt < 2; mt++) {
            const int r0 = wm * 32 + mt * 16 + g;
            #pragma unroll
            for (int nt = 0; nt < 8; nt++) {
                const int col = wn * 64 + nt * 8 + t * 2;
                *(__half2*)(Cb + (size_t)r0 * N + col) =
                    __floats2half2_rn(acc[mt][nt][0], acc[mt][nt][1]);
                *(__half2*)(Cb + (size_t)(r0 + 8) * N + col) =
                    __floats2half2_rn(acc[mt][nt][2], acc[mt][nt][3]);
            }
        }
    } else {
        float* Cb = (float*)Cv + (size_t)m0 * N + n0;
        #pragma unroll
        for (int mt = 0; mt < 2; mt++) {
            const int r0 = wm * 32 + mt * 16 + g;
            #pragma unroll
            for (int nt = 0; nt < 8; nt++) {
                const int col = wn * 64 + nt * 8 + t * 2;
                float b0 = 0.f, b1 = 0.f;
                if (bias) { b0 = bias[n0 + col]; b1 = bias[n0 + col + 1]; }
                *(float2*)(Cb + (size_t)r0 * N + col) =
                    make_float2(acc[mt][nt][0] + b0, acc[mt][nt][1] + b1);
                *(float2*)(Cb + (size_t)(r0 + 8) * N + col) =
                    make_float2(acc[mt][nt][2] + b0, acc[mt][nt][3] + b1);
            }
        }
    }
}

// ---------------------------------------------------------------------------
// Banded flash attention, fp16 MMA, P kept entirely in registers
// (S-accumulator layout == PV A-operand layout; no P smem round-trip).
// SMEM: Q | K[3 stages] | V[3 stages] = 7 x 9216 = 64512 bytes.
// ---------------------------------------------------------------------------
#define AHL 72
#define ABUF (64 * AHL * 2)
#define ATT_SMEM (7 * ABUF)              // 64512

__global__ void __launch_bounds__(128) attn_f16_kernel(
    const __half* __restrict__ qkvh, __half* __restrict__ out)
{
    extern __shared__ __half hs[];
    const uint32_t sb = smem_u32(hs);
    const uint32_t sQ = sb;
    const uint32_t sK = sb + ABUF;           // 3 stages
    const uint32_t sV = sb + 4 * ABUF;       // 3 stages

    const int tid = threadIdx.x;
    const int w = tid >> 5, lane = tid & 31;
    const int g = lane >> 2, t = lane & 3;
    const int q = lane >> 3, rl = lane & 7;
    const int n0 = blockIdx.x * 64;
    const int h  = blockIdx.y;
    const int b  = blockIdx.z;
    const float scale = 0.125f;

    const __half* base = qkvh + (size_t)b * SEQ * 3 * DM + h * HD;

    const int jlo = max(0, n0 - HALF);
    const int jhi = min(SEQ, n0 + 64 + HALF);
    const int NT = (jhi - jlo) >> 6;

    auto load_rows = [&](uint32_t dst, int j0, int sel) {
        #pragma unroll
        for (int i = 0; i < 4; i++) {
            int idx = tid + i * 128;
            int r = idx >> 3, c16 = idx & 7;
            cpa16(dst + (uint32_t)(r * 144 + c16 * 16),
                  base + (size_t)(j0 + r) * 3 * DM + sel * DM + c16 * 8);
        }
    };

    load_rows(sQ, n0, 0);
    load_rows(sK, jlo, 1);
    load_rows(sV, jlo, 2);
    CP_COMMIT();
    if (1 < NT) {
        load_rows(sK + ABUF, jlo + 64, 1);
        load_rows(sV + ABUF, jlo + 64, 2);
    }
    CP_COMMIT();

    const uint32_t aoff = (uint32_t)((16 * w + (q & 1) * 8 + rl) * 144 +
                                     (q >> 1) * 16);
    uint32_t boffK[4], vboff[4];
    #pragma unroll
    for (int jt = 0; jt < 4; jt++)
        boffK[jt] = (uint32_t)(((2 * jt + (q >> 1)) * 8 + rl) * 144 +
                               (q & 1) * 16);
    #pragma unroll
    for (int dt = 0; dt < 4; dt++)
        vboff[dt] = (uint32_t)(((q & 1) * 8 + rl) * 144 + dt * 32 +
                               (q >> 1) * 16);

    float o[8][4];
    #pragma unroll
    for (int dt = 0; dt < 8; dt++)
        #pragma unroll
        for (int r = 0; r < 4; r++) o[dt][r] = 0.f;
    float m0 = -INFINITY, m1 = -INFINITY, l0 = 0.f, l1 = 0.f;

    const int i0 = n0 + w * 16 + g;
    const int i1 = i0 + 8;

    int slot = 0, slot_load = 2;
    for (int c = 0; c < NT; c++) {
        const int j0 = jlo + c * 64;
        CP_WAIT(1);
        __syncthreads();
        if (c + 2 < NT) {
            load_rows(sK + slot_load * ABUF, j0 + 128, 1);
            load_rows(sV + slot_load * ABUF, j0 + 128, 2);
            slot_load = (slot_load + 1 == 3) ? 0 : slot_load + 1;
        }
        CP_COMMIT();

        const uint32_t kslot = sK + slot * ABUF;
        const uint32_t vslot = sV + slot * ABUF;
        slot = (slot + 1 == 3) ? 0 : slot + 1;

        // ---- S = Q @ K^T ----
        float s[8][4];
        #pragma unroll
        for (int nt = 0; nt < 8; nt++)
            #pragma unroll
            for (int r = 0; r < 4; r++) s[nt][r] = 0.f;

        #pragma unroll
        for (int ks = 0; ks < 4; ks++) {
            uint32_t a[4];
            ldsm4(a[0], a[1], a[2], a[3], sQ + aoff + ks * 32);
            #pragma unroll
            for (int jt = 0; jt < 4; jt++) {
                uint32_t b0, b1, b2, b3;
                ldsm4(b0, b1, b2, b3, kslot + boffK[jt] + ks * 32);
                uint32_t be[2] = { b0, b1 }, bo[2] = { b2, b3 };
                mma_f16(s[2 * jt], a, be);
                mma_f16(s[2 * jt + 1], a, bo);
            }
        }

        // ---- scale + mask + online softmax ----
        const bool masked = (j0 - n0 == HALF) || (n0 - j0 == HALF);
        #pragma unroll
        for (int nt = 0; nt < 8; nt++) {
            #pragma unroll
            for (int r = 0; r < 4; r++) s[nt][r] *= scale;
            if (masked) {
                const int jc = j0 + 8 * nt + 2 * t;
                if (abs(i0 - jc) > HALF)       s[nt][0] = -INFINITY;
                if (abs(i0 - (jc + 1)) > HALF) s[nt][1] = -INFINITY;
                if (abs(i1 - jc) > HALF)       s[nt][2] = -INFINITY;
                if (abs(i1 - (jc + 1)) > HALF) s[nt][3] = -INFINITY;
            }
        }
        float mx0 = -INFINITY, mx1 = -INFINITY;
        #pragma unroll
        for (int nt = 0; nt < 8; nt++) {
            mx0 = fmaxf(mx0, fmaxf(s[nt][0], s[nt][1]));
            mx1 = fmaxf(mx1, fmaxf(s[nt][2], s[nt][3]));
        }
        mx0 = fmaxf(mx0, __shfl_xor_sync(0xffffffffu, mx0, 1));
        mx0 = fmaxf(mx0, __shfl_xor_sync(0xffffffffu, mx0, 2));
        mx1 = fmaxf(mx1, __shfl_xor_sync(0xffffffffu, mx1, 1));
        mx1 = fmaxf(mx1, __shfl_xor_sync(0xffffffffu, mx1, 2));
        const float nm0 = fmaxf(m0, mx0), nm1 = fmaxf(m1, mx1);
        const float corr0 = __expf(m0 - nm0), corr1 = __expf(m1 - nm1);
        m0 = nm0; m1 = nm1;

        // exp + pack P directly into PV A-fragments (register-resident)
        float sum0 = 0.f, sum1 = 0.f;
        uint32_t pr[4][4];
        #pragma unroll
        for (int nt = 0; nt < 8; nt++) {
            s[nt][0] = __expf(s[nt][0] - nm0);
            s[nt][1] = __expf(s[nt][1] - nm0);
            s[nt][2] = __expf(s[nt][2] - nm1);
            s[nt][3] = __expf(s[nt][3] - nm1);
            sum0 += s[nt][0] + s[nt][1];
            sum1 += s[nt][2] + s[nt][3];
            const int j = nt >> 1;
            if ((nt & 1) == 0) {
                pr[j][0] = packh2(s[nt][0], s[nt][1]);
                pr[j][1] = packh2(s[nt][2], s[nt][3]);
            } else {
                pr[j][2] = packh2(s[nt][0], s[nt][1]);
                pr[j][3] = packh2(s[nt][2], s[nt][3]);
            }
        }
        sum0 += __shfl_xor_sync(0xffffffffu, sum0, 1);
        sum0 += __shfl_xor_sync(0xffffffffu, sum0, 2);
        sum1 += __shfl_xor_sync(0xffffffffu, sum1, 1);
        sum1 += __shfl_xor_sync(0xffffffffu, sum1, 2);
        l0 = l0 * corr0 + sum0;
        l1 = l1 * corr1 + sum1;
        #pragma unroll
        for (int dt = 0; dt < 8; dt++) {
            o[dt][0] *= corr0; o[dt][1] *= corr0;
            o[dt][2] *= corr1; o[dt][3] *= corr1;
        }

        // ---- O += P @ V (A from registers; V^T via ldmatrix.trans) ----
        #pragma unroll
        for (int ks = 0; ks < 4; ks++) {
            #pragma unroll
            for (int dt = 0; dt < 4; dt++) {
                uint32_t r0, r1, r2, r3;
                ldsm4t(r0, r1, r2, r3, vslot + vboff[dt] + ks * 16 * 144);
                uint32_t be[2] = { r0, r1 }, bo[2] = { r2, r3 };
                mma_f16(o[2 * dt], pr[ks], be);
                mma_f16(o[2 * dt + 1], pr[ks], bo);
            }
        }
    }

    const float inv0 = 1.f / l0, inv1 = 1.f / l1;
    __half* o0 = out + ((size_t)(b * SEQ + i0)) * DM + h * HD;
    __half* o1 = o0 + (size_t)8 * DM;
    #pragma unroll
    for (int dt = 0; dt < 8; dt++) {
        const int col = 8 * dt + 2 * t;
        *(__half2*)(o0 + col) = __floats2half2_rn(o[dt][0] * inv0,
                                                  o[dt][1] * inv0);
        *(__half2*)(o1 + col) = __floats2half2_rn(o[dt][2] * inv1,
                                                  o[dt][3] * inv1);
    }
}

// ---------------------------------------------------------------------------
extern "C" void kernel_launch(void* const* d_in, const int* in_sizes, int n_in,
                              void* d_out, int out_size)
{
    const float* x     = (const float*)d_in[0];
    const float* Wqkv  = (const float*)d_in[1];
    const float* Wproj = (const float*)d_in[2];
    const float* bproj = (const float*)d_in[3];
    float* out = (float*)d_out;

    __half *qkvh, *attnh, *xh, *wqkvh, *wprojh;
    cudaGetSymbolAddress((void**)&qkvh, g_qkvh);
    cudaGetSymbolAddress((void**)&attnh, g_attnh);
    cudaGetSymbolAddress((void**)&xh, g_xh);
    cudaGetSymbolAddress((void**)&wqkvh, g_wqkvh);
    cudaGetSymbolAddress((void**)&wprojh, g_wprojh);

    const int M = BATCH * SEQ;
    cudaFuncSetAttribute(attn_f16_kernel,
                         cudaFuncAttributeMaxDynamicSharedMemorySize,
                         ATT_SMEM);
    cudaFuncSetAttribute(gemm_f16_kernel,
                         cudaFuncAttributeMaxDynamicSharedMemorySize,
                         GEMM_SMEM);

    // 0) prep: one fused f32->f16 convert (x, Wqkv, Wproj)
    {
        const int na = M * DM / 8;
        const int nb = DM * 3 * DM / 8;
        const int nc = DM * DM / 8;
        const int total = na + nb + nc;
        convert3_kernel<<<(total + 255) / 256, 256>>>(
            (const float4*)x,     (uint4*)xh,     na,
            (const float4*)Wqkv,  (uint4*)wqkvh,  nb,
            (const float4*)Wproj, (uint4*)wprojh, nc);
    }
    // 1) QKV projection -> fp16
    {
        dim3 grid(3 * DM / 128, M / 128);
        gemm_f16_kernel<<<grid, 256, GEMM_SMEM>>>(xh, wqkvh, qkvh, nullptr,
                                                  M, 3 * DM, DM, 1);
    }
    // 2) banded attention (register-resident P) -> fp16
    {
        dim3 grid(SEQ / 64, NH, BATCH);
        attn_f16_kernel<<<grid, 128, ATT_SMEM>>>(qkvh, attnh);
    }
    // 3) output projection + bias -> fp32
    {
        dim3 grid(DM / 128, M / 128);
        gemm_f16_kernel<<<grid, 256, GEMM_SMEM>>>(attnh, wprojh, out, bproj,
                                                  M, DM, DM, 0);
    }
}